// round 8
// baseline (speedup 1.0000x reference)
#include <cuda_runtime.h>
#include <cstdint>

#define NROWS 8192
#define DDIM  256

// ---------------- device scratch (allocation-free) ----------------
// tf32-rounded copies, with each 8-column K-group permuted to fragment order
// {0,4,1,5,2,6,3,7} so MMA fragment pairs (k, k+4) are adjacent in memory.
__device__ float g_t[2][NROWS * DDIM];
__device__ float g_sq[2][NROWS];         // exact fp32 row norms

// ---------------- helpers ----------------
__device__ __forceinline__ uint32_t smem_u32(const void* p) {
    uint32_t a;
    asm("{ .reg .u64 t; cvta.to.shared.u64 t, %1; cvt.u32.u64 %0, t; }" : "=r"(a) : "l"(p));
    return a;
}
__device__ __forceinline__ uint2 lds64(uint32_t a) {
    uint2 v;
    asm volatile("ld.shared.v2.b32 {%0,%1}, [%2];" : "=r"(v.x), "=r"(v.y) : "r"(a));
    return v;
}
__device__ __forceinline__ void cp16(uint32_t dst, const void* src) {
    asm volatile("cp.async.cg.shared.global [%0], [%1], 16;" :: "r"(dst), "l"(src));
}
__device__ __forceinline__ void cp_commit() {
    asm volatile("cp.async.commit_group;" ::: "memory");
}
template <int N> __device__ __forceinline__ void cp_wait() {
    asm volatile("cp.async.wait_group %0;" :: "n"(N) : "memory");
}
__device__ __forceinline__ void mma_tf32(float* c, const uint32_t* a, const uint32_t* b) {
    asm volatile(
        "mma.sync.aligned.m16n8k8.row.col.f32.tf32.tf32.f32 "
        "{%0,%1,%2,%3}, {%4,%5,%6,%7}, {%8,%9}, {%0,%1,%2,%3};"
        : "+f"(c[0]), "+f"(c[1]), "+f"(c[2]), "+f"(c[3])
        : "r"(a[0]), "r"(a[1]), "r"(a[2]), "r"(a[3]), "r"(b[0]), "r"(b[1]));
}

// ---------------- prep: tf32-round + K-permute + exact row norms ----------------
__global__ void prep_kernel(const float* __restrict__ x1, const float* __restrict__ x2) {
    __shared__ float buf[8][256];
    int wib   = threadIdx.x >> 5;                              // warp in block
    int gw    = (blockIdx.x * blockDim.x + threadIdx.x) >> 5;  // global warp [0,16384)
    int lane  = threadIdx.x & 31;
    int which = gw >> 13;                 // 0 -> x1, 1 -> x2
    int row   = gw & (NROWS - 1);
    const float4* src = reinterpret_cast<const float4*>((which ? x2 : x1) + (size_t)row * DDIM);

    float s = 0.f;
#pragma unroll
    for (int i = 0; i < 2; i++) {
        int q = lane + 32 * i;            // 64 float4 per row
        float4 v = src[q];
        s += v.x * v.x + v.y * v.y + v.z * v.z + v.w * v.w;   // exact fp32 norm
        *reinterpret_cast<float4*>(&buf[wib][q * 4]) = v;
    }
    __syncwarp();
#pragma unroll
    for (int off = 16; off; off >>= 1) s += __shfl_xor_sync(0xffffffff, s, off);
    if (lane == 0) g_sq[which][row] = s;

    // permuted + tf32-rounded writeback: position p in 8-group holds orig col
    // c = (p&1) ? p/2 + 4 : p/2
    float* dst = &g_t[which][(size_t)row * DDIM];
#pragma unroll
    for (int i = 0; i < 8; i++) {
        int j = i * 32 + lane;
        int p = j & 7;
        int c = (p & 1) ? (p >> 1) + 4 : (p >> 1);
        float v = buf[wib][(j & ~7) + c];
        uint32_t t;
        asm("cvt.rna.tf32.f32 %0, %1;" : "=r"(t) : "f"(v));
        dst[j] = __uint_as_float(t);
    }
}

// ---------------- main GEMM + epilogue ----------------
#define BM 128
#define BN 128
#define BK 32
#define NK (DDIM / BK)            // 8 K-iterations
#define STAGES 3
#define PADB 144                  // 36 floats per smem row -> conflict-free frag reads
#define MAT_BYTES (BM * PADB)     // 18432
#define STAGE_BYTES (2 * MAT_BYTES)
#define SMEM_TOTAL (STAGES * STAGE_BYTES)   // 110592

__global__ void __launch_bounds__(256, 2)
cdist_kernel(float* __restrict__ out) {
    extern __shared__ char smem_raw[];
    const uint32_t sbase = smem_u32(smem_raw);

    const int tid = threadIdx.x;
    const int wid = tid >> 5;
    const int lid = tid & 31;
    const int m0 = blockIdx.y * BM;
    const int n0 = blockIdx.x * BN;
    const int g   = lid >> 2;         // 0..7
    const int tig = lid & 3;          // 0..3
    const int wm = (wid & 1) * 64;    // warp m-offset (2 warps in M)
    const int wn = (wid >> 1) * 32;   // warp n-offset (4 warps in N)

    const float* Ag = g_t[0] + (size_t)m0 * DDIM;
    const float* Bg = g_t[1] + (size_t)n0 * DDIM;

    // per-thread copy coords: 1024 16B chunks per matrix per stage, 4 per thread
    const int cm = tid >> 3;          // base row
    const int kq = tid & 7;           // 16B sub-chunk within 32-float K slice

    auto load_stage = [&](int kc, int s) {
        const uint32_t sA = sbase + (uint32_t)s * STAGE_BYTES;
        const uint32_t sB = sA + MAT_BYTES;
        const size_t gk = (size_t)kc * BK + (size_t)kq * 4;
#pragma unroll
        for (int i = 0; i < 4; i++) {
            int m = cm + i * 32;
            size_t go = (size_t)m * DDIM + gk;
            uint32_t so = (uint32_t)m * PADB + (uint32_t)kq * 16;
            cp16(sA + so, Ag + go);
            cp16(sB + so, Bg + go);
        }
        cp_commit();
    };

    // prologue: STAGES-1 stages in flight
    load_stage(0, 0);
    load_stage(1, 1);

    float c[4][4][4];
#pragma unroll
    for (int mt = 0; mt < 4; mt++)
#pragma unroll
        for (int nt = 0; nt < 4; nt++)
#pragma unroll
            for (int i = 0; i < 4; i++) c[mt][nt][i] = 0.f;

    for (int kc = 0; kc < NK; kc++) {
        cp_wait<STAGES - 2>();     // stage kc landed
        __syncthreads();           // all warps' fills visible; frees oldest buf

        if (kc + STAGES - 1 < NK) load_stage(kc + STAGES - 1, (kc + STAGES - 1) % STAGES);
        else cp_commit();          // empty group keeps wait_group arithmetic uniform

        const uint32_t sA = sbase + (uint32_t)(kc % STAGES) * STAGE_BYTES;
        const uint32_t sB = sA + MAT_BYTES;

#pragma unroll
        for (int ks = 0; ks < 4; ks++) {
            // permuted layout: fragment pair (k=tig, k=tig+4) is contiguous at
            // byte offset ks*32 + tig*8
            const uint32_t koff = (uint32_t)ks * 32u + (uint32_t)tig * 8u;
            uint32_t a[4][4], b[4][2];
#pragma unroll
            for (int mt = 0; mt < 4; mt++) {
                uint32_t r = sA + (uint32_t)(wm + mt * 16 + g) * PADB + koff;
                uint2 lo = lds64(r);
                uint2 hi = lds64(r + 8 * PADB);
                a[mt][0] = lo.x;  a[mt][2] = lo.y;     // (g,   tig), (g,   tig+4)
                a[mt][1] = hi.x;  a[mt][3] = hi.y;     // (g+8, tig), (g+8, tig+4)
            }
#pragma unroll
            for (int nt = 0; nt < 4; nt++) {
                uint32_t r = sB + (uint32_t)(wn + nt * 8 + g) * PADB + koff;
                uint2 bb = lds64(r);
                b[nt][0] = bb.x;  b[nt][1] = bb.y;     // (n=g, k=tig), (n=g, k=tig+4)
            }
#pragma unroll
            for (int mt = 0; mt < 4; mt++)
#pragma unroll
                for (int nt = 0; nt < 4; nt++)
                    mma_tf32(c[mt][nt], a[mt], b[nt]);
        }
    }

    // ---- epilogue: d = sqrt(max(sq1 + sq2 - 2*cross, 0)) ----
    const float* sq1 = g_sq[0] + m0;
    const float* sq2 = g_sq[1] + n0;
#pragma unroll
    for (int mt = 0; mt < 4; mt++) {
        int r0 = wm + mt * 16 + g;
        float s1a = sq1[r0];
        float s1b = sq1[r0 + 8];
        float* o0 = out + (size_t)(m0 + r0) * NROWS + n0;
        float* o1 = o0 + (size_t)8 * NROWS;
#pragma unroll
        for (int nt = 0; nt < 4; nt++) {
            int cc = wn + nt * 8 + 2 * tig;
            float s2a = sq2[cc];
            float s2b = sq2[cc + 1];
            float2 v0, v1;
            v0.x = sqrtf(fmaxf(fmaf(-2.f, c[mt][nt][0], s1a + s2a), 0.f));
            v0.y = sqrtf(fmaxf(fmaf(-2.f, c[mt][nt][1], s1a + s2b), 0.f));
            v1.x = sqrtf(fmaxf(fmaf(-2.f, c[mt][nt][2], s1b + s2a), 0.f));
            v1.y = sqrtf(fmaxf(fmaf(-2.f, c[mt][nt][3], s1b + s2b), 0.f));
            *reinterpret_cast<float2*>(o0 + cc) = v0;
            *reinterpret_cast<float2*>(o1 + cc) = v1;
        }
    }
}

// ---------------- launch ----------------
extern "C" void kernel_launch(void* const* d_in, const int* in_sizes, int n_in,
                              void* d_out, int out_size) {
    (void)in_sizes; (void)n_in; (void)out_size;
    const float* x1 = (const float*)d_in[0];
    const float* x2 = (const float*)d_in[1];
    float* out = (float*)d_out;

    prep_kernel<<<2048, 256>>>(x1, x2);

    static bool attr_set = false;
    if (!attr_set) {
        cudaFuncSetAttribute(cdist_kernel,
                             cudaFuncAttributeMaxDynamicSharedMemorySize, SMEM_TOTAL);
        attr_set = true;
    }
    dim3 grid(NROWS / BN, NROWS / BM);   // (64, 64)
    cdist_kernel<<<grid, 256, SMEM_TOTAL>>>(out);
}

// round 9
// speedup vs baseline: 1.3131x; 1.3131x over previous
#include <cuda_runtime.h>
#include <cstdint>

#define NROWS 8192
#define DDIM  256

// ---------------- device scratch (allocation-free) ----------------
// tf32-rounded copies, with each 8-column K-group permuted to fragment order
// {0,4,1,5,2,6,3,7} so MMA fragment pairs (k, k+4) are adjacent in memory.
__device__ float g_t[2][NROWS * DDIM];
__device__ float g_sq[2][NROWS];         // exact fp32 row norms

// ---------------- helpers ----------------
__device__ __forceinline__ uint32_t smem_u32(const void* p) {
    uint32_t a;
    asm("{ .reg .u64 t; cvta.to.shared.u64 t, %1; cvt.u32.u64 %0, t; }" : "=r"(a) : "l"(p));
    return a;
}
__device__ __forceinline__ uint2 lds64(uint32_t a) {
    uint2 v;
    asm volatile("ld.shared.v2.b32 {%0,%1}, [%2];" : "=r"(v.x), "=r"(v.y) : "r"(a));
    return v;
}
__device__ __forceinline__ void cp16(uint32_t dst, const void* src) {
    asm volatile("cp.async.cg.shared.global [%0], [%1], 16;" :: "r"(dst), "l"(src));
}
__device__ __forceinline__ void cp_commit() {
    asm volatile("cp.async.commit_group;" ::: "memory");
}
template <int N> __device__ __forceinline__ void cp_wait() {
    asm volatile("cp.async.wait_group %0;" :: "n"(N) : "memory");
}
__device__ __forceinline__ void mma_tf32(float* c, const uint32_t* a, const uint32_t* b) {
    asm volatile(
        "mma.sync.aligned.m16n8k8.row.col.f32.tf32.tf32.f32 "
        "{%0,%1,%2,%3}, {%4,%5,%6,%7}, {%8,%9}, {%0,%1,%2,%3};"
        : "+f"(c[0]), "+f"(c[1]), "+f"(c[2]), "+f"(c[3])
        : "r"(a[0]), "r"(a[1]), "r"(a[2]), "r"(a[3]), "r"(b[0]), "r"(b[1]));
}

// ---------------- prep: tf32-round + K-permute + exact row norms ----------------
__global__ void prep_kernel(const float* __restrict__ x1, const float* __restrict__ x2) {
    __shared__ float buf[8][256];
    int wib   = threadIdx.x >> 5;                              // warp in block
    int gw    = (blockIdx.x * blockDim.x + threadIdx.x) >> 5;  // global warp [0,16384)
    int lane  = threadIdx.x & 31;
    int which = gw >> 13;                 // 0 -> x1, 1 -> x2
    int row   = gw & (NROWS - 1);
    const float4* src = reinterpret_cast<const float4*>((which ? x2 : x1) + (size_t)row * DDIM);

    float s = 0.f;
#pragma unroll
    for (int i = 0; i < 2; i++) {
        int q = lane + 32 * i;            // 64 float4 per row
        float4 v = src[q];
        s += v.x * v.x + v.y * v.y + v.z * v.z + v.w * v.w;   // exact fp32 norm
        *reinterpret_cast<float4*>(&buf[wib][q * 4]) = v;
    }
    __syncwarp();
#pragma unroll
    for (int off = 16; off; off >>= 1) s += __shfl_xor_sync(0xffffffff, s, off);
    if (lane == 0) g_sq[which][row] = s;

    // permuted + tf32-rounded writeback: position p in 8-group holds orig col
    // c = (p&1) ? p/2 + 4 : p/2
    float* dst = &g_t[which][(size_t)row * DDIM];
#pragma unroll
    for (int i = 0; i < 8; i++) {
        int j = i * 32 + lane;
        int p = j & 7;
        int c = (p & 1) ? (p >> 1) + 4 : (p >> 1);
        float v = buf[wib][(j & ~7) + c];
        uint32_t t;
        asm("cvt.rna.tf32.f32 %0, %1;" : "=r"(t) : "f"(v));
        dst[j] = __uint_as_float(t);
    }
}

// ---------------- main GEMM + epilogue ----------------
#define BM 128
#define BN 128
#define BK 32
#define NK (DDIM / BK)            // 8 K-iterations
#define STAGES 3
#define ROWB 128                  // 32 floats per smem row, no padding (XOR swizzle)
#define MAT_BYTES (BM * ROWB)     // 16384
#define STAGE_BYTES (2 * MAT_BYTES)
#define SMEM_TOTAL (STAGES * STAGE_BYTES)   // 98304 -> 2 CTAs/SM

__global__ void __launch_bounds__(256, 2)
cdist_kernel(float* __restrict__ out) {
    extern __shared__ char smem_raw[];
    const uint32_t sbase = smem_u32(smem_raw);   // dyn smem is 1KB aligned

    const int tid = threadIdx.x;
    const int wid = tid >> 5;
    const int lid = tid & 31;
    const int m0 = blockIdx.y * BM;
    const int n0 = blockIdx.x * BN;
    const int g   = lid >> 2;         // 0..7
    const int tig = lid & 3;          // 0..3
    const int wm = (wid & 1) * 64;    // warp m-offset (2 warps in M)
    const int wn = (wid >> 1) * 32;   // warp n-offset (4 warps in N)

    const float* Ag = g_t[0] + (size_t)m0 * DDIM;
    const float* Bg = g_t[1] + (size_t)n0 * DDIM;

    // per-thread copy coords: 1024 16B chunks per matrix per stage, 4 per thread
    const int cm = tid >> 3;          // base row
    const int kq = tid & 7;           // 16B sub-chunk within 32-float K slice

    // swizzled store offset within a row: (kq*16) ^ ((row&3)<<5)
    auto load_stage = [&](int kc, int s) {
        const uint32_t sA = sbase + (uint32_t)s * STAGE_BYTES;
        const uint32_t sB = sA + MAT_BYTES;
        const size_t gk = (size_t)kc * BK + (size_t)kq * 4;
#pragma unroll
        for (int i = 0; i < 4; i++) {
            int m = cm + i * 32;
            size_t go = (size_t)m * DDIM + gk;
            uint32_t so = (uint32_t)m * ROWB
                        + (((uint32_t)kq * 16u) ^ (((uint32_t)m & 3u) << 5));
            cp16(sA + so, Ag + go);
            cp16(sB + so, Bg + go);
        }
        cp_commit();
    };

    // prologue: STAGES-1 stages in flight
    load_stage(0, 0);
    load_stage(1, 1);

    float c[4][4][4];
#pragma unroll
    for (int mt = 0; mt < 4; mt++)
#pragma unroll
        for (int nt = 0; nt < 4; nt++)
#pragma unroll
            for (int i = 0; i < 4; i++) c[mt][nt][i] = 0.f;

    for (int kc = 0; kc < NK; kc++) {
        cp_wait<STAGES - 2>();     // stage kc landed
        __syncthreads();           // all warps' fills visible; frees oldest buf

        if (kc + STAGES - 1 < NK) load_stage(kc + STAGES - 1, (kc + STAGES - 1) % STAGES);
        else cp_commit();          // empty group keeps wait_group arithmetic uniform

        const uint32_t sA = sbase + (uint32_t)(kc % STAGES) * STAGE_BYTES;
        const uint32_t sB = sA + MAT_BYTES;

        // per-fragment swizzled base addresses; per-ks address = base ^ (ks<<5)
        // (row*ROWB has bits >=7; ((row&3)<<5) and tig*8 occupy bits 3..6;
        //  ks<<5 flips bits 5..6 only -> pure XOR, no carries)
        uint32_t abase[4], bbase[4];
#pragma unroll
        for (int mt = 0; mt < 4; mt++) {
            uint32_t r = (uint32_t)(wm + mt * 16 + g);
            abase[mt] = sA + r * ROWB + ((r & 3u) << 5) + (uint32_t)tig * 8u;
        }
#pragma unroll
        for (int nt = 0; nt < 4; nt++) {
            uint32_t r = (uint32_t)(wn + nt * 8 + g);
            bbase[nt] = sB + r * ROWB + ((r & 3u) << 5) + (uint32_t)tig * 8u;
        }

#pragma unroll
        for (int ks = 0; ks < 4; ks++) {
            const uint32_t kx = (uint32_t)ks << 5;
            uint32_t a[4][4], b[4][2];
#pragma unroll
            for (int mt = 0; mt < 4; mt++) {
                uint2 lo = lds64(abase[mt] ^ kx);
                uint2 hi = lds64((abase[mt] ^ kx) + 8u * ROWB);   // row+8: same swizzle
                a[mt][0] = lo.x;  a[mt][2] = lo.y;     // (g,   tig), (g,   tig+4)
                a[mt][1] = hi.x;  a[mt][3] = hi.y;     // (g+8, tig), (g+8, tig+4)
            }
#pragma unroll
            for (int nt = 0; nt < 4; nt++) {
                uint2 bb = lds64(bbase[nt] ^ kx);
                b[nt][0] = bb.x;  b[nt][1] = bb.y;     // (n=g, k=tig), (n=g, k=tig+4)
            }
#pragma unroll
            for (int mt = 0; mt < 4; mt++)
#pragma unroll
                for (int nt = 0; nt < 4; nt++)
                    mma_tf32(c[mt][nt], a[mt], b[nt]);
        }
    }

    // ---- epilogue: d = sqrt(max(sq1 + sq2 - 2*cross, 0)) ----
    const float* sq1 = g_sq[0] + m0;
    const float* sq2 = g_sq[1] + n0;
#pragma unroll
    for (int mt = 0; mt < 4; mt++) {
        int r0 = wm + mt * 16 + g;
        float s1a = sq1[r0];
        float s1b = sq1[r0 + 8];
        float* o0 = out + (size_t)(m0 + r0) * NROWS + n0;
        float* o1 = o0 + (size_t)8 * NROWS;
#pragma unroll
        for (int nt = 0; nt < 4; nt++) {
            int cc = wn + nt * 8 + 2 * tig;
            float s2a = sq2[cc];
            float s2b = sq2[cc + 1];
            float2 v0, v1;
            v0.x = sqrtf(fmaxf(fmaf(-2.f, c[mt][nt][0], s1a + s2a), 0.f));
            v0.y = sqrtf(fmaxf(fmaf(-2.f, c[mt][nt][1], s1a + s2b), 0.f));
            v1.x = sqrtf(fmaxf(fmaf(-2.f, c[mt][nt][2], s1b + s2a), 0.f));
            v1.y = sqrtf(fmaxf(fmaf(-2.f, c[mt][nt][3], s1b + s2b), 0.f));
            *reinterpret_cast<float2*>(o0 + cc) = v0;
            *reinterpret_cast<float2*>(o1 + cc) = v1;
        }
    }
}

// ---------------- launch ----------------
extern "C" void kernel_launch(void* const* d_in, const int* in_sizes, int n_in,
                              void* d_out, int out_size) {
    (void)in_sizes; (void)n_in; (void)out_size;
    const float* x1 = (const float*)d_in[0];
    const float* x2 = (const float*)d_in[1];
    float* out = (float*)d_out;

    prep_kernel<<<2048, 256>>>(x1, x2);

    static bool attr_set = false;
    if (!attr_set) {
        cudaFuncSetAttribute(cdist_kernel,
                             cudaFuncAttributeMaxDynamicSharedMemorySize, SMEM_TOTAL);
        attr_set = true;
    }
    dim3 grid(NROWS / BN, NROWS / BM);   // (64, 64)
    cdist_kernel<<<grid, 256, SMEM_TOTAL>>>(out);
}